// round 3
// baseline (speedup 1.0000x reference)
#include <cuda_runtime.h>
#include <cuda_bf16.h>
#include <stdint.h>

#define DEV __device__ __forceinline__

static constexpr int Bn  = 8192;
static constexpr int DIN = 1024;
static constexpr int Dd  = 768;
static constexpr int Cc  = 16384;

// ---- scratch: device globals (no allocation allowed) ----
__device__ __align__(1024) __nv_bfloat16 g_Xb[(size_t)Bn * DIN];
__device__ __align__(1024) __nv_bfloat16 g_Wb[(size_t)Dd * DIN];   // W^T
__device__ __align__(1024) __nv_bfloat16 g_Cb[(size_t)Cc * Dd];
__device__ __align__(1024) __nv_bfloat16 g_E [(size_t)Bn * Dd];
__device__ float g_esq[Bn];
__device__ float g_csq[Cc];

// ---------------- PTX helpers (all legal at compute_103 base) ----------------
DEV uint32_t smem_u32(const void* p){
    uint32_t a;
    asm("{ .reg .u64 t; cvta.to.shared.u64 t, %1; cvt.u32.u64 %0, t; }" : "=r"(a) : "l"(p));
    return a;
}
DEV uint32_t swz(uint32_t off){ return off ^ ((off >> 3) & 0x70); }   // SW128
DEV void cp16(uint32_t dst, const void* src){
    asm volatile("cp.async.cg.shared.global [%0], [%1], 16;" :: "r"(dst), "l"(src) : "memory");
}
DEV void cp_commit(){ asm volatile("cp.async.commit_group;" ::: "memory"); }
template<int N> DEV void cp_wait(){ asm volatile("cp.async.wait_group %0;" :: "n"(N) : "memory"); }

DEV void ldsm4(uint32_t& r0, uint32_t& r1, uint32_t& r2, uint32_t& r3, uint32_t addr){
    asm volatile("ldmatrix.sync.aligned.m8n8.x4.shared.b16 {%0,%1,%2,%3}, [%4];"
                 : "=r"(r0), "=r"(r1), "=r"(r2), "=r"(r3) : "r"(addr));
}
DEV void mma16816(float* c, const uint32_t* a, uint32_t b0, uint32_t b1){
    asm volatile(
        "mma.sync.aligned.m16n8k16.row.col.f32.bf16.bf16.f32 "
        "{%0,%1,%2,%3}, {%4,%5,%6,%7}, {%8,%9}, {%0,%1,%2,%3};"
        : "+f"(c[0]), "+f"(c[1]), "+f"(c[2]), "+f"(c[3])
        : "r"(a[0]), "r"(a[1]), "r"(a[2]), "r"(a[3]), "r"(b0), "r"(b1));
}

// ---------------- prep kernels ----------------
__global__ void prep_x(const float4* __restrict__ x){
    size_t i = (size_t)blockIdx.x * blockDim.x + threadIdx.x;
    float4 v = x[i];
    reinterpret_cast<__nv_bfloat162*>(g_Xb)[2*i]   = __floats2bfloat162_rn(v.x, v.y);
    reinterpret_cast<__nv_bfloat162*>(g_Xb)[2*i+1] = __floats2bfloat162_rn(v.z, v.w);
}

__global__ void prep_w(const float* __restrict__ W){
    __shared__ float t[32][33];
    const int bx = blockIdx.x, by = blockIdx.y;      // bx: n-tile (24), by: k-tile (32)
    const int tx = threadIdx.x, ty = threadIdx.y;    // (32,8)
    #pragma unroll
    for (int i = 0; i < 32; i += 8)
        t[ty + i][tx] = W[(size_t)(by*32 + ty + i)*Dd + bx*32 + tx];
    __syncthreads();
    #pragma unroll
    for (int i = 0; i < 32; i += 8)
        g_Wb[(size_t)(bx*32 + ty + i)*DIN + by*32 + tx] = __float2bfloat16(t[tx][ty + i]);
}

__global__ void prep_cent(const float* __restrict__ cent){
    const int row = blockIdx.x, tid = threadIdx.x;
    const float* src = cent + (size_t)row * Dd;
    __nv_bfloat16* dst = g_Cb + (size_t)row * Dd;
    float s = 0.f;
    for (int j = tid; j < Dd; j += 256){
        float v = src[j];
        s += v * v;
        dst[j] = __float2bfloat16(v);
    }
    __shared__ float red[8];
    #pragma unroll
    for (int o = 16; o; o >>= 1) s += __shfl_down_sync(0xffffffffu, s, o);
    if ((tid & 31) == 0) red[tid >> 5] = s;
    __syncthreads();
    if (tid < 8){
        s = red[tid];
        #pragma unroll
        for (int o = 4; o; o >>= 1) s += __shfl_down_sync(0xffu, s, o);
        if (tid == 0) g_csq[row] = s;
    }
}

__global__ void prep_esq(){
    const int row = blockIdx.x, tid = threadIdx.x;
    const __nv_bfloat16* src = g_E + (size_t)row * Dd;
    float s = 0.f;
    for (int j = tid; j < Dd; j += 256){
        float v = __bfloat162float(src[j]);
        s += v * v;
    }
    __shared__ float red[8];
    #pragma unroll
    for (int o = 16; o; o >>= 1) s += __shfl_down_sync(0xffffffffu, s, o);
    if ((tid & 31) == 0) red[tid >> 5] = s;
    __syncthreads();
    if (tid < 8){
        s = red[tid];
        #pragma unroll
        for (int o = 4; o; o >>= 1) s += __shfl_down_sync(0xffu, s, o);
        if (tid == 0) g_esq[row] = s;
    }
}

// ---------------- mma.sync GEMM: 128x128 CTA tile, BK=64, double-buffered ----------------
// MODE 0: E[8192,768] = Xb @ Wb^T, store bf16
// MODE 1: out[8192,16384] = 2*(E @ Cb^T) - esq - csq, store fp32
static constexpr int STAGE = 128 * 128 * 2;          // A(16KB) + B(16KB)
static constexpr int SMEM_BYTES = 2 * STAGE;         // 65536

template<int MODE>
__global__ void __launch_bounds__(256, 2)
gemm_ws(const __nv_bfloat16* __restrict__ A, const __nv_bfloat16* __restrict__ B,
        float* __restrict__ out)
{
    constexpr int K     = (MODE == 0) ? DIN : Dd;
    constexpr int NT    = K / 64;                    // k-chunks (16 / 12)
    constexpr int LDA   = K * 2;                     // bytes per row
    constexpr int NCOLS = (MODE == 0) ? Dd : Cc;

    extern __shared__ char smem[];
    const uint32_t sb = smem_u32(smem);
    const int tid = threadIdx.x, wid = tid >> 5, lane = tid & 31;
    const int warp_m = wid >> 2, warp_n = wid & 3;   // 2 x 4 warps
    const int m0 = blockIdx.x * 128, n0 = blockIdx.y * 128;

    const char* gA = reinterpret_cast<const char*>(A) + (size_t)m0 * LDA;
    const char* gB = reinterpret_cast<const char*>(B) + (size_t)n0 * LDA;

    auto load_stage = [&](int kc){
        const uint32_t base = sb + (kc & 1) * STAGE;
        const size_t koff = (size_t)kc * 128;        // 64 bf16 = 128 B
        const int row = tid >> 1;                    // 0..127
        const int c   = (tid & 1) * 4;               // chunk base (2 chunks of 4x16B)
        #pragma unroll
        for (int q = 0; q < 4; q++)                  // A: 128 rows x 8 chunks
            cp16(base + swz((uint32_t)(row*128 + (c+q)*16)), gA + (size_t)row*LDA + koff + (c+q)*16);
        #pragma unroll
        for (int q = 0; q < 4; q++)                  // B: 128 rows x 8 chunks
            cp16(base + 16384 + swz((uint32_t)(row*128 + (c+q)*16)), gB + (size_t)row*LDA + koff + (c+q)*16);
        cp_commit();
    };

    float acc[4][4][4];
    #pragma unroll
    for (int i = 0; i < 4; i++)
        #pragma unroll
        for (int j = 0; j < 4; j++)
            #pragma unroll
            for (int r = 0; r < 4; r++) acc[i][j][r] = 0.f;

    load_stage(0);
    load_stage(1);

    const int lrow = lane & 15, lcol = (lane >> 4) * 16;

    for (int kc = 0; kc < NT; kc++){
        cp_wait<1>();
        __syncthreads();
        const uint32_t base = sb + (kc & 1) * STAGE;
        #pragma unroll
        for (int ks = 0; ks < 4; ks++){
            uint32_t a[4][4], b[2][4];
            const uint32_t cb = ks*32 + lcol;
            #pragma unroll
            for (int i = 0; i < 4; i++)
                ldsm4(a[i][0], a[i][1], a[i][2], a[i][3],
                      base + swz((uint32_t)((warp_m*64 + i*16 + lrow)*128 + cb)));
            #pragma unroll
            for (int j = 0; j < 2; j++)
                ldsm4(b[j][0], b[j][1], b[j][2], b[j][3],
                      base + 16384 + swz((uint32_t)((warp_n*32 + j*16 + lrow)*128 + cb)));
            #pragma unroll
            for (int i = 0; i < 4; i++)
                #pragma unroll
                for (int j2 = 0; j2 < 4; j2++)
                    mma16816(acc[i][j2], a[i], b[j2>>1][j2&1], b[j2>>1][2 + (j2&1)]);
        }
        __syncthreads();
        if (kc + 2 < NT) load_stage(kc + 2);
    }

    // ---------------- epilogue ----------------
    const int quad = lane >> 2, tq = lane & 3;
    #pragma unroll
    for (int i = 0; i < 4; i++){
        const int mr0 = m0 + warp_m*64 + i*16 + quad;
        if (MODE == 0){
            #pragma unroll
            for (int j2 = 0; j2 < 4; j2++){
                const int n = n0 + warp_n*32 + j2*8 + tq*2;
                *reinterpret_cast<__nv_bfloat162*>(g_E + (size_t)mr0 * NCOLS + n) =
                    __floats2bfloat162_rn(acc[i][j2][0], acc[i][j2][1]);
                *reinterpret_cast<__nv_bfloat162*>(g_E + (size_t)(mr0+8) * NCOLS + n) =
                    __floats2bfloat162_rn(acc[i][j2][2], acc[i][j2][3]);
            }
        } else {
            const float e0 = __ldg(&g_esq[mr0]), e1 = __ldg(&g_esq[mr0 + 8]);
            #pragma unroll
            for (int j2 = 0; j2 < 4; j2++){
                const int n = n0 + warp_n*32 + j2*8 + tq*2;
                const float cs0 = __ldg(&g_csq[n]), cs1 = __ldg(&g_csq[n+1]);
                float2 v0 = make_float2(2.f*acc[i][j2][0] - e0 - cs0,
                                        2.f*acc[i][j2][1] - e0 - cs1);
                float2 v1 = make_float2(2.f*acc[i][j2][2] - e1 - cs0,
                                        2.f*acc[i][j2][3] - e1 - cs1);
                *reinterpret_cast<float2*>(out + (size_t)mr0 * NCOLS + n)     = v0;
                *reinterpret_cast<float2*>(out + (size_t)(mr0+8) * NCOLS + n) = v1;
            }
        }
    }
}

extern "C" void kernel_launch(void* const* d_in, const int* in_sizes, int n_in,
                              void* d_out, int out_size)
{
    const float* x = (const float*)d_in[0];
    const float* W = (const float*)d_in[1];
    const float* c = (const float*)d_in[2];
    float* out = (float*)d_out;

    cudaFuncSetAttribute(gemm_ws<0>, cudaFuncAttributeMaxDynamicSharedMemorySize, SMEM_BYTES);
    cudaFuncSetAttribute(gemm_ws<1>, cudaFuncAttributeMaxDynamicSharedMemorySize, SMEM_BYTES);

    prep_x<<<(Bn * DIN / 4) / 256, 256>>>(reinterpret_cast<const float4*>(x));
    prep_w<<<dim3(Dd / 32, DIN / 32), dim3(32, 8)>>>(W);
    prep_cent<<<Cc, 256>>>(c);

    __nv_bfloat16 *xb, *wb, *cb, *eb;
    cudaGetSymbolAddress((void**)&xb, g_Xb);
    cudaGetSymbolAddress((void**)&wb, g_Wb);
    cudaGetSymbolAddress((void**)&cb, g_Cb);
    cudaGetSymbolAddress((void**)&eb, g_E);

    gemm_ws<0><<<dim3(Bn / 128, Dd / 128), 256, SMEM_BYTES>>>(xb, wb, nullptr);
    prep_esq<<<Bn, 256>>>();
    gemm_ws<1><<<dim3(Bn / 128, Cc / 128), 256, SMEM_BYTES>>>(eb, cb, out);
}

// round 4
// speedup vs baseline: 1.2633x; 1.2633x over previous
#include <cuda_runtime.h>
#include <cuda_bf16.h>
#include <stdint.h>

#define DEV __device__ __forceinline__

static constexpr int Bn  = 8192;
static constexpr int DIN = 1024;
static constexpr int Dd  = 768;
static constexpr int Cc  = 16384;

// ---- scratch: device globals (no allocation allowed) ----
__device__ __align__(1024) __nv_bfloat16 g_Xb[(size_t)Bn * DIN];
__device__ __align__(1024) __nv_bfloat16 g_Wb[(size_t)Dd * DIN];   // W^T
__device__ __align__(1024) __nv_bfloat16 g_Cb[(size_t)Cc * Dd];
__device__ __align__(1024) __nv_bfloat16 g_E [(size_t)Bn * Dd];
__device__ float g_esq[Bn];
__device__ float g_csq[Cc];

// ---------------- PTX helpers ----------------
DEV uint32_t smem_u32(const void* p){
    uint32_t a;
    asm("{ .reg .u64 t; cvta.to.shared.u64 t, %1; cvt.u32.u64 %0, t; }" : "=r"(a) : "l"(p));
    return a;
}
DEV uint32_t swz(uint32_t off){ return off ^ ((off >> 3) & 0x70); }   // SW128
DEV void cp16(uint32_t dst, const void* src){
    asm volatile("cp.async.cg.shared.global [%0], [%1], 16;" :: "r"(dst), "l"(src) : "memory");
}
DEV void cp_commit(){ asm volatile("cp.async.commit_group;" ::: "memory"); }
template<int N> DEV void cp_wait(){ asm volatile("cp.async.wait_group %0;" :: "n"(N) : "memory"); }

DEV void ldsm4(uint32_t& r0, uint32_t& r1, uint32_t& r2, uint32_t& r3, uint32_t addr){
    asm volatile("ldmatrix.sync.aligned.m8n8.x4.shared.b16 {%0,%1,%2,%3}, [%4];"
                 : "=r"(r0), "=r"(r1), "=r"(r2), "=r"(r3) : "r"(addr));
}
DEV void mma16816(float* c, const uint32_t* a, uint32_t b0, uint32_t b1){
    asm volatile(
        "mma.sync.aligned.m16n8k16.row.col.f32.bf16.bf16.f32 "
        "{%0,%1,%2,%3}, {%4,%5,%6,%7}, {%8,%9}, {%0,%1,%2,%3};"
        : "+f"(c[0]), "+f"(c[1]), "+f"(c[2]), "+f"(c[3])
        : "r"(a[0]), "r"(a[1]), "r"(a[2]), "r"(a[3]), "r"(b0), "r"(b1));
}

// ---------------- prep kernels ----------------
__global__ void prep_x(const float4* __restrict__ x){
    size_t i = (size_t)blockIdx.x * blockDim.x + threadIdx.x;
    float4 v = x[i];
    reinterpret_cast<__nv_bfloat162*>(g_Xb)[2*i]   = __floats2bfloat162_rn(v.x, v.y);
    reinterpret_cast<__nv_bfloat162*>(g_Xb)[2*i+1] = __floats2bfloat162_rn(v.z, v.w);
}

__global__ void prep_w(const float* __restrict__ W){
    __shared__ float t[32][33];
    const int bx = blockIdx.x, by = blockIdx.y;
    const int tx = threadIdx.x, ty = threadIdx.y;    // (32,8)
    #pragma unroll
    for (int i = 0; i < 32; i += 8)
        t[ty + i][tx] = W[(size_t)(by*32 + ty + i)*Dd + bx*32 + tx];
    __syncthreads();
    #pragma unroll
    for (int i = 0; i < 32; i += 8)
        g_Wb[(size_t)(bx*32 + ty + i)*DIN + by*32 + tx] = __float2bfloat16(t[tx][ty + i]);
}

__global__ void prep_cent(const float* __restrict__ cent){
    const int row = blockIdx.x, tid = threadIdx.x;
    const float* src = cent + (size_t)row * Dd;
    __nv_bfloat16* dst = g_Cb + (size_t)row * Dd;
    float s = 0.f;
    for (int j = tid; j < Dd; j += 256){
        float v = src[j];
        s += v * v;
        dst[j] = __float2bfloat16(v);
    }
    __shared__ float red[8];
    #pragma unroll
    for (int o = 16; o; o >>= 1) s += __shfl_down_sync(0xffffffffu, s, o);
    if ((tid & 31) == 0) red[tid >> 5] = s;
    __syncthreads();
    if (tid < 8){
        s = red[tid];
        #pragma unroll
        for (int o = 4; o; o >>= 1) s += __shfl_down_sync(0xffu, s, o);
        if (tid == 0) g_csq[row] = s;
    }
}

__global__ void prep_esq(){
    const int row = blockIdx.x, tid = threadIdx.x;
    const __nv_bfloat16* src = g_E + (size_t)row * Dd;
    float s = 0.f;
    for (int j = tid; j < Dd; j += 256){
        float v = __bfloat162float(src[j]);
        s += v * v;
    }
    __shared__ float red[8];
    #pragma unroll
    for (int o = 16; o; o >>= 1) s += __shfl_down_sync(0xffffffffu, s, o);
    if ((tid & 31) == 0) red[tid >> 5] = s;
    __syncthreads();
    if (tid < 8){
        s = red[tid];
        #pragma unroll
        for (int o = 4; o; o >>= 1) s += __shfl_down_sync(0xffu, s, o);
        if (tid == 0) g_esq[row] = s;
    }
}

// ------- mma.sync GEMM: CTA 128x256, warp 64x64 (2x4 warps), BK=64, 4 stages -------
// MODE 0: E[8192,768] = Xb @ Wb^T, store bf16
// MODE 1: out[8192,16384] = 2*(E @ Cb^T) - esq - csq, store fp32
static constexpr int A_ST   = 128 * 128;             // 16 KB
static constexpr int B_ST   = 256 * 128;             // 32 KB
static constexpr int STAGE  = A_ST + B_ST;           // 48 KB
static constexpr int NSTG   = 4;
static constexpr int SMEM_BYTES = NSTG * STAGE;      // 192 KB

template<int MODE>
__global__ void __launch_bounds__(256, 1)
gemm_ws(const __nv_bfloat16* __restrict__ A, const __nv_bfloat16* __restrict__ B,
        float* __restrict__ out)
{
    constexpr int K     = (MODE == 0) ? DIN : Dd;
    constexpr int NT    = K / 64;                    // 16 / 12 k-chunks
    constexpr int LD    = K * 2;                     // bytes per row
    constexpr int NCOLS = (MODE == 0) ? Dd : Cc;

    extern __shared__ char smem[];
    const uint32_t sb = smem_u32(smem);
    const int tid = threadIdx.x, wid = tid >> 5, lane = tid & 31;
    const int warp_m = wid >> 2, warp_n = wid & 3;   // 2 x 4
    const int m0 = blockIdx.x * 128, n0 = blockIdx.y * 256;

    const char* gA = reinterpret_cast<const char*>(A) + (size_t)m0 * LD;
    const char* gB = reinterpret_cast<const char*>(B) + (size_t)n0 * LD;

    auto load_stage = [&](int kc){
        const uint32_t base = sb + (kc & (NSTG-1)) * STAGE;
        const size_t koff = (size_t)kc * 128;        // 64 bf16 = 128 B
        #pragma unroll
        for (int i = 0; i < 4; i++){                 // A: 128 rows x 8 chunks
            const int t = tid + i * 256, row = t >> 3, c = t & 7;
            cp16(base + swz((uint32_t)(row*128 + c*16)), gA + (size_t)row*LD + koff + c*16);
        }
        #pragma unroll
        for (int i = 0; i < 8; i++){                 // B: 256 rows x 8 chunks
            const int t = tid + i * 256, row = t >> 3, c = t & 7;
            cp16(base + A_ST + swz((uint32_t)(row*128 + c*16)), gB + (size_t)row*LD + koff + c*16);
        }
        cp_commit();
    };

    float acc[4][8][4];
    #pragma unroll
    for (int i = 0; i < 4; i++)
        #pragma unroll
        for (int j = 0; j < 8; j++)
            #pragma unroll
            for (int r = 0; r < 4; r++) acc[i][j][r] = 0.f;

    load_stage(0); load_stage(1); load_stage(2);

    const int lrow = lane & 15, lcol = (lane >> 4) * 16;

    for (int kc = 0; kc < NT; kc++){
        cp_wait<2>();
        __syncthreads();
        if (kc + 3 < NT) load_stage(kc + 3);
        else             cp_commit();                 // keep group counting uniform
        const uint32_t base = sb + (kc & (NSTG-1)) * STAGE;
        #pragma unroll
        for (int ks = 0; ks < 4; ks++){
            uint32_t a[4][4], b[4][4];
            const uint32_t cb = ks*32 + lcol;
            #pragma unroll
            for (int i = 0; i < 4; i++)
                ldsm4(a[i][0], a[i][1], a[i][2], a[i][3],
                      base + swz((uint32_t)((warp_m*64 + i*16 + lrow)*128 + cb)));
            #pragma unroll
            for (int j = 0; j < 4; j++)
                ldsm4(b[j][0], b[j][1], b[j][2], b[j][3],
                      base + A_ST + swz((uint32_t)((warp_n*64 + j*16 + lrow)*128 + cb)));
            #pragma unroll
            for (int i = 0; i < 4; i++)
                #pragma unroll
                for (int j2 = 0; j2 < 8; j2++)
                    mma16816(acc[i][j2], a[i], b[j2>>1][j2&1], b[j2>>1][2 + (j2&1)]);
        }
    }

    // ---------------- epilogue ----------------
    const int quad = lane >> 2, tq = lane & 3;
    #pragma unroll
    for (int i = 0; i < 4; i++){
        const int mr0 = m0 + warp_m*64 + i*16 + quad;
        if (MODE == 0){
            #pragma unroll
            for (int j2 = 0; j2 < 8; j2++){
                const int n = n0 + warp_n*64 + j2*8 + tq*2;
                *reinterpret_cast<__nv_bfloat162*>(g_E + (size_t)mr0 * NCOLS + n) =
                    __floats2bfloat162_rn(acc[i][j2][0], acc[i][j2][1]);
                *reinterpret_cast<__nv_bfloat162*>(g_E + (size_t)(mr0+8) * NCOLS + n) =
                    __floats2bfloat162_rn(acc[i][j2][2], acc[i][j2][3]);
            }
        } else {
            const float e0 = __ldg(&g_esq[mr0]), e1 = __ldg(&g_esq[mr0 + 8]);
            #pragma unroll
            for (int j2 = 0; j2 < 8; j2++){
                const int n = n0 + warp_n*64 + j2*8 + tq*2;
                const float cs0 = __ldg(&g_csq[n]), cs1 = __ldg(&g_csq[n+1]);
                float2 v0 = make_float2(2.f*acc[i][j2][0] - e0 - cs0,
                                        2.f*acc[i][j2][1] - e0 - cs1);
                float2 v1 = make_float2(2.f*acc[i][j2][2] - e1 - cs0,
                                        2.f*acc[i][j2][3] - e1 - cs1);
                *reinterpret_cast<float2*>(out + (size_t)mr0 * NCOLS + n)     = v0;
                *reinterpret_cast<float2*>(out + (size_t)(mr0+8) * NCOLS + n) = v1;
            }
        }
    }
}

extern "C" void kernel_launch(void* const* d_in, const int* in_sizes, int n_in,
                              void* d_out, int out_size)
{
    const float* x = (const float*)d_in[0];
    const float* W = (const float*)d_in[1];
    const float* c = (const float*)d_in[2];
    float* out = (float*)d_out;

    cudaFuncSetAttribute(gemm_ws<0>, cudaFuncAttributeMaxDynamicSharedMemorySize, SMEM_BYTES);
    cudaFuncSetAttribute(gemm_ws<1>, cudaFuncAttributeMaxDynamicSharedMemorySize, SMEM_BYTES);

    prep_x<<<(Bn * DIN / 4) / 256, 256>>>(reinterpret_cast<const float4*>(x));
    prep_w<<<dim3(Dd / 32, DIN / 32), dim3(32, 8)>>>(W);
    prep_cent<<<Cc, 256>>>(c);

    __nv_bfloat16 *xb, *wb, *cb, *eb;
    cudaGetSymbolAddress((void**)&xb, g_Xb);
    cudaGetSymbolAddress((void**)&wb, g_Wb);
    cudaGetSymbolAddress((void**)&cb, g_Cb);
    cudaGetSymbolAddress((void**)&eb, g_E);

    gemm_ws<0><<<dim3(Bn / 128, Dd / 256), 256, SMEM_BYTES>>>(xb, wb, nullptr);
    prep_esq<<<Bn, 256>>>();
    gemm_ws<1><<<dim3(Bn / 128, Cc / 256), 256, SMEM_BYTES>>>(eb, cb, out);
}

// round 5
// speedup vs baseline: 1.2675x; 1.0033x over previous
#include <cuda_runtime.h>
#include <cuda_bf16.h>
#include <stdint.h>

#define DEV __device__ __forceinline__

static constexpr int Bn  = 8192;
static constexpr int DIN = 1024;
static constexpr int Dd  = 768;
static constexpr int Cc  = 16384;

// ---- scratch: device globals (no allocation allowed) ----
__device__ __align__(1024) __nv_bfloat16 g_Xb[(size_t)Bn * DIN];
__device__ __align__(1024) __nv_bfloat16 g_Wb[(size_t)Dd * DIN];   // W^T
__device__ __align__(1024) __nv_bfloat16 g_Cb[(size_t)Cc * Dd];
__device__ __align__(1024) __nv_bfloat16 g_E [(size_t)Bn * Dd];
__device__ float g_esq[Bn];
__device__ float g_csq[Cc];

// ---------------- PTX helpers ----------------
DEV uint32_t smem_u32(const void* p){
    uint32_t a;
    asm("{ .reg .u64 t; cvta.to.shared.u64 t, %1; cvt.u32.u64 %0, t; }" : "=r"(a) : "l"(p));
    return a;
}
DEV uint32_t swz(uint32_t off){ return off ^ ((off >> 3) & 0x70); }   // SW128
DEV void cp16(uint32_t dst, const void* src){
    asm volatile("cp.async.cg.shared.global [%0], [%1], 16;" :: "r"(dst), "l"(src) : "memory");
}
DEV void cp_commit(){ asm volatile("cp.async.commit_group;" ::: "memory"); }
template<int N> DEV void cp_wait(){ asm volatile("cp.async.wait_group %0;" :: "n"(N) : "memory"); }

DEV void ldsm4(uint32_t& r0, uint32_t& r1, uint32_t& r2, uint32_t& r3, uint32_t addr){
    asm volatile("ldmatrix.sync.aligned.m8n8.x4.shared.b16 {%0,%1,%2,%3}, [%4];"
                 : "=r"(r0), "=r"(r1), "=r"(r2), "=r"(r3) : "r"(addr));
}
DEV void mma16816(float* c, const uint32_t* a, uint32_t b0, uint32_t b1){
    asm volatile(
        "mma.sync.aligned.m16n8k16.row.col.f32.bf16.bf16.f32 "
        "{%0,%1,%2,%3}, {%4,%5,%6,%7}, {%8,%9}, {%0,%1,%2,%3};"
        : "+f"(c[0]), "+f"(c[1]), "+f"(c[2]), "+f"(c[3])
        : "r"(a[0]), "r"(a[1]), "r"(a[2]), "r"(a[3]), "r"(b0), "r"(b1));
}

// ---------------- prep kernels ----------------
__global__ void prep_x(const float4* __restrict__ x){
    size_t i = (size_t)blockIdx.x * blockDim.x + threadIdx.x;
    float4 v = x[i];
    reinterpret_cast<__nv_bfloat162*>(g_Xb)[2*i]   = __floats2bfloat162_rn(v.x, v.y);
    reinterpret_cast<__nv_bfloat162*>(g_Xb)[2*i+1] = __floats2bfloat162_rn(v.z, v.w);
}

__global__ void prep_w(const float* __restrict__ W){
    __shared__ float t[32][33];
    const int bx = blockIdx.x, by = blockIdx.y;
    const int tx = threadIdx.x, ty = threadIdx.y;    // (32,8)
    #pragma unroll
    for (int i = 0; i < 32; i += 8)
        t[ty + i][tx] = W[(size_t)(by*32 + ty + i)*Dd + bx*32 + tx];
    __syncthreads();
    #pragma unroll
    for (int i = 0; i < 32; i += 8)
        g_Wb[(size_t)(bx*32 + ty + i)*DIN + by*32 + tx] = __float2bfloat16(t[tx][ty + i]);
}

__global__ void prep_cent(const float* __restrict__ cent){
    const int row = blockIdx.x, tid = threadIdx.x;
    const float* src = cent + (size_t)row * Dd;
    __nv_bfloat16* dst = g_Cb + (size_t)row * Dd;
    float s = 0.f;
    for (int j = tid; j < Dd; j += 256){
        float v = src[j];
        s += v * v;
        dst[j] = __float2bfloat16(v);
    }
    __shared__ float red[8];
    #pragma unroll
    for (int o = 16; o; o >>= 1) s += __shfl_down_sync(0xffffffffu, s, o);
    if ((tid & 31) == 0) red[tid >> 5] = s;
    __syncthreads();
    if (tid < 8){
        s = red[tid];
        #pragma unroll
        for (int o = 4; o; o >>= 1) s += __shfl_down_sync(0xffu, s, o);
        if (tid == 0) g_csq[row] = s;
    }
}

__global__ void prep_esq(){
    const int row = blockIdx.x, tid = threadIdx.x;
    const __nv_bfloat16* src = g_E + (size_t)row * Dd;
    float s = 0.f;
    for (int j = tid; j < Dd; j += 256){
        float v = __bfloat162float(src[j]);
        s += v * v;
    }
    __shared__ float red[8];
    #pragma unroll
    for (int o = 16; o; o >>= 1) s += __shfl_down_sync(0xffffffffu, s, o);
    if ((tid & 31) == 0) red[tid >> 5] = s;
    __syncthreads();
    if (tid < 8){
        s = red[tid];
        #pragma unroll
        for (int o = 4; o; o >>= 1) s += __shfl_down_sync(0xffu, s, o);
        if (tid == 0) g_csq[0] = g_csq[0];  // no-op guard (never taken path removed)
    }
    if (tid < 8){
        // (reduction tail)
    }
    // final write handled below
    if (tid == 0){
        // recompute warp-0 reduction result is already in red[0..7] summed above
    }
}

// NOTE: prep_esq above got mangled during edit — define the real one:
__global__ void prep_esq2(){
    const int row = blockIdx.x, tid = threadIdx.x;
    const __nv_bfloat16* src = g_E + (size_t)row * Dd;
    float s = 0.f;
    for (int j = tid; j < Dd; j += 256){
        float v = __bfloat162float(src[j]);
        s += v * v;
    }
    __shared__ float red[8];
    #pragma unroll
    for (int o = 16; o; o >>= 1) s += __shfl_down_sync(0xffffffffu, s, o);
    if ((tid & 31) == 0) red[tid >> 5] = s;
    __syncthreads();
    if (tid < 8){
        s = red[tid];
        #pragma unroll
        for (int o = 4; o; o >>= 1) s += __shfl_down_sync(0xffu, s, o);
        if (tid == 0) g_esq[row] = s;
    }
}

// ---- mma.sync GEMM: CTA 128x256, 16 warps (4x4), warp tile 32x64, BK=64, 4 stages ----
// MODE 0: E[8192,768] = Xb @ Wb^T, store bf16
// MODE 1: out[8192,16384] = 2*(E @ Cb^T) - esq - csq, store fp32
static constexpr int A_ST   = 128 * 128;             // 16 KB
static constexpr int B_ST   = 256 * 128;             // 32 KB
static constexpr int STAGE  = A_ST + B_ST;           // 48 KB
static constexpr int NSTG   = 4;
static constexpr int SMEM_BYTES = NSTG * STAGE;      // 192 KB

template<int MODE>
__global__ void __launch_bounds__(512, 1)
gemm_ws(const __nv_bfloat16* __restrict__ A, const __nv_bfloat16* __restrict__ B,
        float* __restrict__ out)
{
    constexpr int K     = (MODE == 0) ? DIN : Dd;
    constexpr int NT    = K / 64;                    // 16 / 12 k-chunks
    constexpr int LD    = K * 2;                     // bytes per row
    constexpr int NCOLS = (MODE == 0) ? Dd : Cc;

    extern __shared__ char smem[];
    const uint32_t sb = smem_u32(smem);
    const int tid = threadIdx.x, wid = tid >> 5, lane = tid & 31;
    const int warp_m = wid >> 2, warp_n = wid & 3;   // 4 x 4
    const int m0 = blockIdx.x * 128, n0 = blockIdx.y * 256;

    const char* gA = reinterpret_cast<const char*>(A) + (size_t)m0 * LD;
    const char* gB = reinterpret_cast<const char*>(B) + (size_t)n0 * LD;

    auto load_stage = [&](int kc){
        const uint32_t base = sb + (kc & (NSTG-1)) * STAGE;
        const size_t koff = (size_t)kc * 128;        // 64 bf16 = 128 B
        #pragma unroll
        for (int i = 0; i < 2; i++){                 // A: 128 rows x 8 chunks = 1024
            const int t = tid + i * 512, row = t >> 3, c = t & 7;
            cp16(base + swz((uint32_t)(row*128 + c*16)), gA + (size_t)row*LD + koff + c*16);
        }
        #pragma unroll
        for (int i = 0; i < 4; i++){                 // B: 256 rows x 8 chunks = 2048
            const int t = tid + i * 512, row = t >> 3, c = t & 7;
            cp16(base + A_ST + swz((uint32_t)(row*128 + c*16)), gB + (size_t)row*LD + koff + c*16);
        }
        cp_commit();
    };

    float acc[2][8][4];
    #pragma unroll
    for (int i = 0; i < 2; i++)
        #pragma unroll
        for (int j = 0; j < 8; j++)
            #pragma unroll
            for (int r = 0; r < 4; r++) acc[i][j][r] = 0.f;

    load_stage(0); load_stage(1); load_stage(2);

    const int lrow = lane & 15, lcol = (lane >> 4) * 16;

    for (int kc = 0; kc < NT; kc++){
        cp_wait<2>();
        __syncthreads();
        if (kc + 3 < NT) load_stage(kc + 3);
        else             cp_commit();                 // keep group counting uniform
        const uint32_t base = sb + (kc & (NSTG-1)) * STAGE;
        #pragma unroll
        for (int ks = 0; ks < 4; ks++){
            uint32_t a[2][4], b[4][4];
            const uint32_t cb = ks*32 + lcol;
            #pragma unroll
            for (int i = 0; i < 2; i++)
                ldsm4(a[i][0], a[i][1], a[i][2], a[i][3],
                      base + swz((uint32_t)((warp_m*32 + i*16 + lrow)*128 + cb)));
            #pragma unroll
            for (int j = 0; j < 4; j++)
                ldsm4(b[j][0], b[j][1], b[j][2], b[j][3],
                      base + A_ST + swz((uint32_t)((warp_n*64 + j*16 + lrow)*128 + cb)));
            #pragma unroll
            for (int i = 0; i < 2; i++)
                #pragma unroll
                for (int j2 = 0; j2 < 8; j2++)
                    mma16816(acc[i][j2], a[i], b[j2>>1][j2&1], b[j2>>1][2 + (j2&1)]);
        }
    }

    // ---------------- epilogue ----------------
    const int quad = lane >> 2, tq = lane & 3;
    #pragma unroll
    for (int i = 0; i < 2; i++){
        const int mr0 = m0 + warp_m*32 + i*16 + quad;
        if (MODE == 0){
            #pragma unroll
            for (int j2 = 0; j2 < 8; j2++){
                const int n = n0 + warp_n*64 + j2*8 + tq*2;
                *reinterpret_cast<__nv_bfloat162*>(g_E + (size_t)mr0 * NCOLS + n) =
                    __floats2bfloat162_rn(acc[i][j2][0], acc[i][j2][1]);
                *reinterpret_cast<__nv_bfloat162*>(g_E + (size_t)(mr0+8) * NCOLS + n) =
                    __floats2bfloat162_rn(acc[i][j2][2], acc[i][j2][3]);
            }
        } else {
            const float e0 = __ldg(&g_esq[mr0]), e1 = __ldg(&g_esq[mr0 + 8]);
            #pragma unroll
            for (int j2 = 0; j2 < 8; j2++){
                const int n = n0 + warp_n*64 + j2*8 + tq*2;
                const float cs0 = __ldg(&g_csq[n]), cs1 = __ldg(&g_csq[n+1]);
                float2 v0 = make_float2(2.f*acc[i][j2][0] - e0 - cs0,
                                        2.f*acc[i][j2][1] - e0 - cs1);
                float2 v1 = make_float2(2.f*acc[i][j2][2] - e1 - cs0,
                                        2.f*acc[i][j2][3] - e1 - cs1);
                *reinterpret_cast<float2*>(out + (size_t)mr0 * NCOLS + n)     = v0;
                *reinterpret_cast<float2*>(out + (size_t)(mr0+8) * NCOLS + n) = v1;
            }
        }
    }
}

extern "C" void kernel_launch(void* const* d_in, const int* in_sizes, int n_in,
                              void* d_out, int out_size)
{
    const float* x = (const float*)d_in[0];
    const float* W = (const float*)d_in[1];
    const float* c = (const float*)d_in[2];
    float* out = (float*)d_out;

    cudaFuncSetAttribute(gemm_ws<0>, cudaFuncAttributeMaxDynamicSharedMemorySize, SMEM_BYTES);
    cudaFuncSetAttribute(gemm_ws<1>, cudaFuncAttributeMaxDynamicSharedMemorySize, SMEM_BYTES);

    prep_x<<<(Bn * DIN / 4) / 256, 256>>>(reinterpret_cast<const float4*>(x));
    prep_w<<<dim3(Dd / 32, DIN / 32), dim3(32, 8)>>>(W);
    prep_cent<<<Cc, 256>>>(c);

    __nv_bfloat16 *xb, *wb, *cb, *eb;
    cudaGetSymbolAddress((void**)&xb, g_Xb);
    cudaGetSymbolAddress((void**)&wb, g_Wb);
    cudaGetSymbolAddress((void**)&cb, g_Cb);
    cudaGetSymbolAddress((void**)&eb, g_E);

    gemm_ws<0><<<dim3(Bn / 128, Dd / 256), 512, SMEM_BYTES>>>(xb, wb, nullptr);
    prep_esq2<<<Bn, 256>>>();
    gemm_ws<1><<<dim3(Bn / 128, Cc / 256), 512, SMEM_BYTES>>>(eb, cb, out);
}